// round 9
// baseline (speedup 1.0000x reference)
#include <cuda_runtime.h>
#include <cuda_fp16.h>
#include <math.h>
#include <stdint.h>

#define DD 1024
#define EE 8
#define BBATCH 4
#define SSEQ 4096
#define MM (BBATCH*SSEQ)

#define NPOOL 32
#define SCH (SSEQ/NPOOL)   // 128 sequence rows per pool1 block

// -------- scratch (no allocations allowed) --------
__device__ float g_part[NPOOL*BBATCH*DD];
__device__ float g_pooled[BBATCH*DD];
__device__ float g_w[EE];
__device__ __half g_ah[(size_t)MM*DD];   // A * 1024, fp16 hi
__device__ __half g_al[(size_t)MM*DD];   // A * 1024 residual, fp16 lo
__device__ __half g_wh[(size_t)DD*DD];   // merged W * 1024, fp16
__device__ float g_mb[DD];

// ============================================================
// pool1: mean-partials over S  +  fused A split to fp16 hi/lo (x1024)
// ============================================================
__global__ void pool1_kernel(const float* __restrict__ in) {
    const int chunk = blockIdx.x;
    const int b = blockIdx.y;
    const int d4 = threadIdx.x;  // 0..255 (float4 column group)
    const int r0 = b*SSEQ + chunk*SCH;
    const float4* p = reinterpret_cast<const float4*>(in) + (size_t)r0*(DD/4) + d4;
    float sx=0.f, sy=0.f, sz=0.f, sw=0.f;
    for (int s = 0; s < SCH; s++) {
        float4 v = p[(size_t)s*(DD/4)];
        sx += v.x; sy += v.y; sz += v.z; sw += v.w;
        // split: h = fp16(v*1024), l = fp16(v*1024 - h)
        float ax = v.x*1024.f, ay = v.y*1024.f, az = v.z*1024.f, aw = v.w*1024.f;
        __half2 h01 = __floats2half2_rn(ax, ay);
        __half2 h23 = __floats2half2_rn(az, aw);
        float2 f01 = __half22float2(h01);
        float2 f23 = __half22float2(h23);
        __half2 l01 = __floats2half2_rn(ax - f01.x, ay - f01.y);
        __half2 l23 = __floats2half2_rn(az - f23.x, aw - f23.y);
        const size_t o = (size_t)(r0 + s)*DD + d4*4;
        *(uint2*)(g_ah + o) = make_uint2(*(uint32_t*)&h01, *(uint32_t*)&h23);
        *(uint2*)(g_al + o) = make_uint2(*(uint32_t*)&l01, *(uint32_t*)&l23);
    }
    reinterpret_cast<float4*>(g_part)[(chunk*BBATCH + b)*(DD/4) + d4]
        = make_float4(sx, sy, sz, sw);
}

__global__ void pool2_kernel() {
    const int i = blockIdx.x*256 + threadIdx.x;
    float sx=0.f, sy=0.f, sz=0.f, sw=0.f;
    #pragma unroll
    for (int c = 0; c < NPOOL; c++) {
        float4 v = reinterpret_cast<const float4*>(g_part)[c*(BBATCH*DD/4) + i];
        sx += v.x; sy += v.y; sz += v.z; sw += v.w;
    }
    const float inv = 1.0f / (float)SSEQ;
    reinterpret_cast<float4*>(g_pooled)[i] = make_float4(sx*inv, sy*inv, sz*inv, sw*inv);
}

// ============================================================
// router: logits -> softmax -> batch mean
// ============================================================
__global__ void router_kernel(const float* __restrict__ rw, const float* __restrict__ rb) {
    __shared__ float sprob[BBATCH][EE];
    const int warp = threadIdx.x >> 5;
    const int lane = threadIdx.x & 31;
    const int b = warp >> 3;
    const int e = warp & 7;
    float sum = 0.f;
    for (int d = lane; d < DD; d += 32)
        sum = fmaf(g_pooled[b*DD + d], rw[e*DD + d], sum);
    #pragma unroll
    for (int o = 16; o; o >>= 1) sum += __shfl_xor_sync(0xffffffffu, sum, o);
    if (lane == 0) sprob[b][e] = sum + rb[e];
    __syncthreads();
    if (threadIdx.x < BBATCH) {
        const int bb = threadIdx.x;
        float mx = sprob[bb][0];
        #pragma unroll
        for (int ee = 1; ee < EE; ee++) mx = fmaxf(mx, sprob[bb][ee]);
        float ex[EE]; float den = 0.f;
        #pragma unroll
        for (int ee = 0; ee < EE; ee++) { ex[ee] = expf(sprob[bb][ee] - mx); den += ex[ee]; }
        #pragma unroll
        for (int ee = 0; ee < EE; ee++) sprob[bb][ee] = ex[ee] / den;
    }
    __syncthreads();
    if (threadIdx.x < EE) {
        float a = 0.f;
        #pragma unroll
        for (int bb = 0; bb < BBATCH; bb++) a += sprob[bb][threadIdx.x];
        g_w[threadIdx.x] = a * (1.0f / (float)BBATCH);
    }
}

// ============================================================
// merge: g_wh = fp16(1024 * sum_e w[e]*expert_w[e]), g_mb fp32
// ============================================================
__global__ void merge_kernel(const float* __restrict__ ew, const float* __restrict__ eb) {
    float w[EE];
    #pragma unroll
    for (int e = 0; e < EE; e++) w[e] = g_w[e];
    const size_t i = (size_t)blockIdx.x*256 + threadIdx.x;  // float4 index
    float sx=0.f, sy=0.f, sz=0.f, sw=0.f;
    #pragma unroll
    for (int e = 0; e < EE; e++) {
        float4 v = reinterpret_cast<const float4*>(ew)[(size_t)e*(DD*(size_t)DD/4) + i];
        sx = fmaf(w[e], v.x, sx); sy = fmaf(w[e], v.y, sy);
        sz = fmaf(w[e], v.z, sz); sw = fmaf(w[e], v.w, sw);
    }
    __half2 h01 = __floats2half2_rn(sx*1024.f, sy*1024.f);
    __half2 h23 = __floats2half2_rn(sz*1024.f, sw*1024.f);
    *(uint2*)(g_wh + i*4) = make_uint2(*(uint32_t*)&h01, *(uint32_t*)&h23);
    if (i < DD/4) {
        float bx=0.f, by=0.f, bz=0.f, bw=0.f;
        #pragma unroll
        for (int e = 0; e < EE; e++) {
            float4 v = reinterpret_cast<const float4*>(eb)[e*(DD/4) + i];
            bx = fmaf(w[e], v.x, bx); by = fmaf(w[e], v.y, by);
            bz = fmaf(w[e], v.z, bz); bw = fmaf(w[e], v.w, bw);
        }
        reinterpret_cast<float4*>(g_mb)[i] = make_float4(bx, by, bz, bw);
    }
}

// ============================================================
// GEMM: C = (Ah+Al) x Wh^T * 2^-20 + b     (fp16 mma, fp32 acc)
// CTA 128x128, 8 warps of 64x32, BK=32, cp.async double buffer, 2 CTA/SM
// ============================================================

#define BKC 32
#define NKCH (DD/BKC)            // 32
#define PITCH 80                 // 64B data + 16B pad per 32-col fp16 row
#define TILE_B (128*PITCH)       // 10240
#define BUF_B (3*TILE_B)         // Ah, Al, Wh
#define GEMM_SMEM (2*BUF_B)      // 61440

__device__ __forceinline__ uint32_t smem_u32(const void* p) {
    uint32_t a;
    asm("{ .reg .u64 t; cvta.to.shared.u64 t, %1; cvt.u32.u64 %0, t; }" : "=r"(a) : "l"(p));
    return a;
}
__device__ __forceinline__ void cp16(uint32_t dst, const void* src) {
    asm volatile("cp.async.cg.shared.global [%0], [%1], 16;" :: "r"(dst), "l"(src));
}
#define CP_COMMIT() asm volatile("cp.async.commit_group;" ::: "memory")

__device__ __forceinline__ void mma16816(float acc[4], const uint32_t a[4], const uint32_t b[2]) {
    asm volatile(
        "mma.sync.aligned.m16n8k16.row.col.f32.f16.f16.f32 "
        "{%0,%1,%2,%3}, {%4,%5,%6,%7}, {%8,%9}, {%0,%1,%2,%3};"
        : "+f"(acc[0]), "+f"(acc[1]), "+f"(acc[2]), "+f"(acc[3])
        : "r"(a[0]), "r"(a[1]), "r"(a[2]), "r"(a[3]), "r"(b[0]), "r"(b[1]));
}

// A fragments: 4 m-tiles (64 rows), k-offset kk
__device__ __forceinline__ void ldA(uint32_t fr[4][4], const char* As, int wm, int g, int t, int kk) {
    #pragma unroll
    for (int mt = 0; mt < 4; mt++) {
        const char* base = As + (wm*64 + mt*16)*PITCH + (kk + 2*t)*2;
        fr[mt][0] = *(const uint32_t*)(base + g*PITCH);
        fr[mt][1] = *(const uint32_t*)(base + (g+8)*PITCH);
        fr[mt][2] = *(const uint32_t*)(base + g*PITCH + 16);
        fr[mt][3] = *(const uint32_t*)(base + (g+8)*PITCH + 16);
    }
}
// B fragments: 4 n-tiles (32 cols); W [n][k] row-major == col-major B
__device__ __forceinline__ void ldB(uint32_t fr[4][2], const char* Ws, int wn, int g, int t, int kk) {
    #pragma unroll
    for (int nt = 0; nt < 4; nt++) {
        const char* base = Ws + (wn*32 + nt*8 + g)*PITCH + (kk + 2*t)*2;
        fr[nt][0] = *(const uint32_t*)(base);
        fr[nt][1] = *(const uint32_t*)(base + 16);
    }
}

__global__ __launch_bounds__(256, 2) void gemm_mma(float* __restrict__ C) {
    extern __shared__ char sm[];
    const uint32_t sb = smem_u32(sm);
    const int tid = threadIdx.x;
    const int w = tid >> 5;
    const int lane = tid & 31;
    const int wm = w >> 2;          // 0..1
    const int wn = w & 3;           // 0..3
    const int g = lane >> 2;        // 0..7
    const int t = lane & 3;         // 0..3
    const int m0 = blockIdx.y << 7;
    const int n0 = blockIdx.x << 7;

    // cp.async mapping: row = tid&127, col-seg c in {cb, cb+2}; 5r+c distinct mod 8 -> conflict-free
    const int crow = tid & 127;
    const int cb = tid >> 7;

#define ISSUE(kb) do {                                                        \
    const uint32_t bufb = sb + ((kb) & 1)*BUF_B;                              \
    const int ko = (kb)*BKC;                                                  \
    const __half* pah = g_ah + (size_t)(m0 + crow)*DD + ko;                   \
    const __half* pal = g_al + (size_t)(m0 + crow)*DD + ko;                   \
    const __half* pwh = g_wh + (size_t)(n0 + crow)*DD + ko;                   \
    _Pragma("unroll")                                                         \
    for (int j = 0; j < 2; j++) {                                             \
        const int c = cb + 2*j;                                               \
        const uint32_t d = bufb + crow*PITCH + c*16;                          \
        cp16(d,            pah + c*8);                                        \
        cp16(d + TILE_B,   pal + c*8);                                        \
        cp16(d + 2*TILE_B, pwh + c*8);                                        \
    }                                                                         \
} while (0)

    float acc[4][4][4];
    #pragma unroll
    for (int mt = 0; mt < 4; mt++)
        #pragma unroll
        for (int nt = 0; nt < 4; nt++)
            #pragma unroll
            for (int c = 0; c < 4; c++) acc[mt][nt][c] = 0.f;

    ISSUE(0); CP_COMMIT();
    ISSUE(1); CP_COMMIT();

    for (int kb = 0; kb < NKCH; kb++) {
        if (kb + 1 < NKCH) asm volatile("cp.async.wait_group 1;" ::: "memory");
        else               asm volatile("cp.async.wait_group 0;" ::: "memory");
        __syncthreads();

        const char* base = sm + (kb & 1)*BUF_B;
        uint32_t af[4][4], bf[4][2];
        #pragma unroll
        for (int kk = 0; kk < BKC; kk += 16) {
            ldB(bf, base + 2*TILE_B, wn, g, t, kk);
            ldA(af, base, wm, g, t, kk);                 // Ah
            #pragma unroll
            for (int mt = 0; mt < 4; mt++)
                #pragma unroll
                for (int nt = 0; nt < 4; nt++)
                    mma16816(acc[mt][nt], af[mt], bf[nt]);
            ldA(af, base + TILE_B, wm, g, t, kk);        // Al (reuse bf)
            #pragma unroll
            for (int mt = 0; mt < 4; mt++)
                #pragma unroll
                for (int nt = 0; nt < 4; nt++)
                    mma16816(acc[mt][nt], af[mt], bf[nt]);
        }
        __syncthreads();
        if (kb + 2 < NKCH) { ISSUE(kb + 2); CP_COMMIT(); }
    }

    // epilogue: undo 2^20 scale, add bias, store
    const float SC = 1.0f / (1024.0f * 1024.0f);
    #pragma unroll
    for (int nt = 0; nt < 4; nt++) {
        const int col = n0 + wn*32 + nt*8 + 2*t;
        const float b0 = g_mb[col];
        const float b1 = g_mb[col + 1];
        #pragma unroll
        for (int mt = 0; mt < 4; mt++) {
            const int row0 = m0 + wm*64 + mt*16 + g;
            float2 v0 = make_float2(fmaf(acc[mt][nt][0], SC, b0), fmaf(acc[mt][nt][1], SC, b1));
            float2 v1 = make_float2(fmaf(acc[mt][nt][2], SC, b0), fmaf(acc[mt][nt][3], SC, b1));
            *(float2*)(C + (size_t)row0*DD + col)       = v0;
            *(float2*)(C + (size_t)(row0 + 8)*DD + col) = v1;
        }
    }
#undef ISSUE
}

// ============================================================
// launch
// ============================================================
extern "C" void kernel_launch(void* const* d_in, const int* in_sizes, int n_in,
                              void* d_out, int out_size) {
    const float* inputs   = (const float*)d_in[0];
    const float* router_w = (const float*)d_in[1];
    const float* router_b = (const float*)d_in[2];
    const float* expert_w = (const float*)d_in[3];
    const float* expert_b = (const float*)d_in[4];
    float* out = (float*)d_out;

    cudaFuncSetAttribute(gemm_mma, cudaFuncAttributeMaxDynamicSharedMemorySize, GEMM_SMEM);

    pool1_kernel<<<dim3(NPOOL, BBATCH), 256>>>(inputs);
    pool2_kernel<<<(BBATCH*DD/4)/256, 256>>>();
    router_kernel<<<1, 1024>>>(router_w, router_b);
    merge_kernel<<<(DD*DD/4)/256, 256>>>(expert_w, expert_b);
    gemm_mma<<<dim3(DD/128, MM/128), 256, GEMM_SMEM>>>(out);
}

// round 12
// speedup vs baseline: 1.5334x; 1.5334x over previous
#include <cuda_runtime.h>
#include <cuda_fp16.h>
#include <math.h>
#include <stdint.h>

#define DD 1024
#define EE 8
#define BBATCH 4
#define SSEQ 4096
#define MM (BBATCH*SSEQ)

#define NPOOL 32
#define SCH (SSEQ/NPOOL)

// -------- scratch (no allocations allowed) --------
__device__ float g_part[NPOOL*BBATCH*DD];
__device__ float g_pooled[BBATCH*DD];
__device__ float g_w[EE];
__device__ __half g_ah[(size_t)MM*DD];   // A * 1024, fp16
__device__ __half g_wh[(size_t)DD*DD];   // merged W * 1024, fp16
__device__ float g_mb[DD];

// ============================================================
// pool1: mean-partials over S + fused A->fp16 (x1024)
// ============================================================
__global__ void pool1_kernel(const float* __restrict__ in) {
    const int chunk = blockIdx.x;
    const int b = blockIdx.y;
    const int d4 = threadIdx.x;  // 0..255
    const int r0 = b*SSEQ + chunk*SCH;
    const float4* p = reinterpret_cast<const float4*>(in) + (size_t)r0*(DD/4) + d4;
    float sx=0.f, sy=0.f, sz=0.f, sw=0.f;
    for (int s = 0; s < SCH; s++) {
        float4 v = p[(size_t)s*(DD/4)];
        sx += v.x; sy += v.y; sz += v.z; sw += v.w;
        __half2 h01 = __floats2half2_rn(v.x*1024.f, v.y*1024.f);
        __half2 h23 = __floats2half2_rn(v.z*1024.f, v.w*1024.f);
        *(uint2*)(g_ah + (size_t)(r0 + s)*DD + d4*4)
            = make_uint2(*(uint32_t*)&h01, *(uint32_t*)&h23);
    }
    reinterpret_cast<float4*>(g_part)[(chunk*BBATCH + b)*(DD/4) + d4]
        = make_float4(sx, sy, sz, sw);
}

__global__ void pool2_kernel() {
    const int i = blockIdx.x*256 + threadIdx.x;
    float sx=0.f, sy=0.f, sz=0.f, sw=0.f;
    #pragma unroll
    for (int c = 0; c < NPOOL; c++) {
        float4 v = reinterpret_cast<const float4*>(g_part)[c*(BBATCH*DD/4) + i];
        sx += v.x; sy += v.y; sz += v.z; sw += v.w;
    }
    const float inv = 1.0f / (float)SSEQ;
    reinterpret_cast<float4*>(g_pooled)[i] = make_float4(sx*inv, sy*inv, sz*inv, sw*inv);
}

// ============================================================
// router
// ============================================================
__global__ void router_kernel(const float* __restrict__ rw, const float* __restrict__ rb) {
    __shared__ float sprob[BBATCH][EE];
    const int warp = threadIdx.x >> 5;
    const int lane = threadIdx.x & 31;
    const int b = warp >> 3;
    const int e = warp & 7;
    float sum = 0.f;
    for (int d = lane; d < DD; d += 32)
        sum = fmaf(g_pooled[b*DD + d], rw[e*DD + d], sum);
    #pragma unroll
    for (int o = 16; o; o >>= 1) sum += __shfl_xor_sync(0xffffffffu, sum, o);
    if (lane == 0) sprob[b][e] = sum + rb[e];
    __syncthreads();
    if (threadIdx.x < BBATCH) {
        const int bb = threadIdx.x;
        float mx = sprob[bb][0];
        #pragma unroll
        for (int ee = 1; ee < EE; ee++) mx = fmaxf(mx, sprob[bb][ee]);
        float ex[EE]; float den = 0.f;
        #pragma unroll
        for (int ee = 0; ee < EE; ee++) { ex[ee] = expf(sprob[bb][ee] - mx); den += ex[ee]; }
        #pragma unroll
        for (int ee = 0; ee < EE; ee++) sprob[bb][ee] = ex[ee] / den;
    }
    __syncthreads();
    if (threadIdx.x < EE) {
        float a = 0.f;
        #pragma unroll
        for (int bb = 0; bb < BBATCH; bb++) a += sprob[bb][threadIdx.x];
        g_w[threadIdx.x] = a * (1.0f / (float)BBATCH);
    }
}

// ============================================================
// merge: g_wh = fp16(1024 * sum_e w[e]*ew[e]), g_mb fp32
// ============================================================
__global__ void merge_kernel(const float* __restrict__ ew, const float* __restrict__ eb) {
    float w[EE];
    #pragma unroll
    for (int e = 0; e < EE; e++) w[e] = g_w[e];
    const size_t i = (size_t)blockIdx.x*256 + threadIdx.x;
    float sx=0.f, sy=0.f, sz=0.f, sw=0.f;
    #pragma unroll
    for (int e = 0; e < EE; e++) {
        float4 v = reinterpret_cast<const float4*>(ew)[(size_t)e*(DD*(size_t)DD/4) + i];
        sx = fmaf(w[e], v.x, sx); sy = fmaf(w[e], v.y, sy);
        sz = fmaf(w[e], v.z, sz); sw = fmaf(w[e], v.w, sw);
    }
    __half2 h01 = __floats2half2_rn(sx*1024.f, sy*1024.f);
    __half2 h23 = __floats2half2_rn(sz*1024.f, sw*1024.f);
    *(uint2*)(g_wh + i*4) = make_uint2(*(uint32_t*)&h01, *(uint32_t*)&h23);
    if (i < DD/4) {
        float bx=0.f, by=0.f, bz=0.f, bw=0.f;
        #pragma unroll
        for (int e = 0; e < EE; e++) {
            float4 v = reinterpret_cast<const float4*>(eb)[e*(DD/4) + i];
            bx = fmaf(w[e], v.x, bx); by = fmaf(w[e], v.y, by);
            bz = fmaf(w[e], v.z, bz); bw = fmaf(w[e], v.w, bw);
        }
        reinterpret_cast<float4*>(g_mb)[i] = make_float4(bx, by, bz, bw);
    }
}

// ============================================================
// GEMM: C = Ah x Wh^T * 2^-20 + b   (fp16 mma, fp32 acc)
// CTA 128x128, BK=64, 3-stage cp.async, 8 warps 64x32, 2 CTA/SM
// ============================================================

#define BKC 64
#define NKCH (DD/BKC)            // 16
#define PITCH 144                // 128B data + 16B pad per 64-col fp16 row
#define TILE_B (128*PITCH)       // 18432
#define STAGE_B (2*TILE_B)       // 36864 (Ah + Wh)
#define GEMM_SMEM (3*STAGE_B)    // 110592

__device__ __forceinline__ uint32_t smem_u32(const void* p) {
    uint32_t a;
    asm("{ .reg .u64 t; cvta.to.shared.u64 t, %1; cvt.u32.u64 %0, t; }" : "=r"(a) : "l"(p));
    return a;
}
__device__ __forceinline__ void cp16(uint32_t dst, const void* src) {
    asm volatile("cp.async.cg.shared.global [%0], [%1], 16;" :: "r"(dst), "l"(src));
}
#define CP_COMMIT() asm volatile("cp.async.commit_group;" ::: "memory")

__device__ __forceinline__ void mma16816(float acc[4], const uint32_t a[4], const uint32_t b[2]) {
    asm volatile(
        "mma.sync.aligned.m16n8k16.row.col.f32.f16.f16.f32 "
        "{%0,%1,%2,%3}, {%4,%5,%6,%7}, {%8,%9}, {%0,%1,%2,%3};"
        : "+f"(acc[0]), "+f"(acc[1]), "+f"(acc[2]), "+f"(acc[3])
        : "r"(a[0]), "r"(a[1]), "r"(a[2]), "r"(a[3]), "r"(b[0]), "r"(b[1]));
}

__device__ __forceinline__ void ldA(uint32_t fr[4][4], const char* As, int wm, int g, int t, int kk) {
    #pragma unroll
    for (int mt = 0; mt < 4; mt++) {
        const char* base = As + (wm*64 + mt*16)*PITCH + (kk + 2*t)*2;
        fr[mt][0] = *(const uint32_t*)(base + g*PITCH);
        fr[mt][1] = *(const uint32_t*)(base + (g+8)*PITCH);
        fr[mt][2] = *(const uint32_t*)(base + g*PITCH + 16);
        fr[mt][3] = *(const uint32_t*)(base + (g+8)*PITCH + 16);
    }
}
__device__ __forceinline__ void ldB(uint32_t fr[4][2], const char* Ws, int wn, int g, int t, int kk) {
    #pragma unroll
    for (int nt = 0; nt < 4; nt++) {
        const char* base = Ws + (wn*32 + nt*8 + g)*PITCH + (kk + 2*t)*2;
        fr[nt][0] = *(const uint32_t*)(base);
        fr[nt][1] = *(const uint32_t*)(base + 16);
    }
}

__global__ __launch_bounds__(256, 2) void gemm_mma(float* __restrict__ C) {
    extern __shared__ char sm[];
    const uint32_t sb = smem_u32(sm);
    const int tid = threadIdx.x;
    const int w = tid >> 5;
    const int lane = tid & 31;
    const int wm = w >> 2;
    const int wn = w & 3;
    const int g = lane >> 2;
    const int t = lane & 3;
    const int m0 = blockIdx.y << 7;
    const int n0 = blockIdx.x << 7;

    // loader: each thread owns one row of one operand, 8x 16B segments
    const int crow = tid & 127;
    const int cop = tid >> 7;   // 0: Ah, 1: Wh
    const __half* grow = cop ? (g_wh + (size_t)(n0 + crow)*DD)
                             : (g_ah + (size_t)(m0 + crow)*DD);

#define ISSUE(kb) do {                                                        \
    const uint32_t d0 = sb + ((kb) % 3)*STAGE_B + cop*TILE_B + crow*PITCH;    \
    const __half* s0 = grow + (kb)*BKC;                                       \
    _Pragma("unroll")                                                         \
    for (int j = 0; j < 8; j++) cp16(d0 + j*16, s0 + j*8);                    \
} while (0)

    float acc[4][4][4];
    #pragma unroll
    for (int mt = 0; mt < 4; mt++)
        #pragma unroll
        for (int nt = 0; nt < 4; nt++)
            #pragma unroll
            for (int c = 0; c < 4; c++) acc[mt][nt][c] = 0.f;

    ISSUE(0); CP_COMMIT();
    ISSUE(1); CP_COMMIT();
    ISSUE(2); CP_COMMIT();

    for (int kb = 0; kb < NKCH; kb++) {
        if (kb < NKCH - 2)      asm volatile("cp.async.wait_group 2;" ::: "memory");
        else if (kb == NKCH-2)  asm volatile("cp.async.wait_group 1;" ::: "memory");
        else                    asm volatile("cp.async.wait_group 0;" ::: "memory");
        __syncthreads();

        const char* base = sm + (kb % 3)*STAGE_B;
        uint32_t af[4][4], bf[4][2];
        #pragma unroll
        for (int kk = 0; kk < BKC; kk += 16) {
            ldB(bf, base + TILE_B, wn, g, t, kk);
            ldA(af, base, wm, g, t, kk);
            #pragma unroll
            for (int mt = 0; mt < 4; mt++)
                #pragma unroll
                for (int nt = 0; nt < 4; nt++)
                    mma16816(acc[mt][nt], af[mt], bf[nt]);
        }
        __syncthreads();
        if (kb + 3 < NKCH) { ISSUE(kb + 3); CP_COMMIT(); }
    }

    // epilogue: undo 2^20 scale, add bias, store
    const float SC = 1.0f / (1024.0f * 1024.0f);
    #pragma unroll
    for (int nt = 0; nt < 4; nt++) {
        const int col = n0 + wn*32 + nt*8 + 2*t;
        const float b0 = g_mb[col];
        const float b1 = g_mb[col + 1];
        #pragma unroll
        for (int mt = 0; mt < 4; mt++) {
            const int row0 = m0 + wm*64 + mt*16 + g;
            float2 v0 = make_float2(fmaf(acc[mt][nt][0], SC, b0), fmaf(acc[mt][nt][1], SC, b1));
            float2 v1 = make_float2(fmaf(acc[mt][nt][2], SC, b0), fmaf(acc[mt][nt][3], SC, b1));
            *(float2*)(C + (size_t)row0*DD + col)       = v0;
            *(float2*)(C + (size_t)(row0 + 8)*DD + col) = v1;
        }
    }
#undef ISSUE
}

// ============================================================
// launch
// ============================================================
extern "C" void kernel_launch(void* const* d_in, const int* in_sizes, int n_in,
                              void* d_out, int out_size) {
    const float* inputs   = (const float*)d_in[0];
    const float* router_w = (const float*)d_in[1];
    const float* router_b = (const float*)d_in[2];
    const float* expert_w = (const float*)d_in[3];
    const float* expert_b = (const float*)d_in[4];
    float* out = (float*)d_out;

    cudaFuncSetAttribute(gemm_mma, cudaFuncAttributeMaxDynamicSharedMemorySize, GEMM_SMEM);

    pool1_kernel<<<dim3(NPOOL, BBATCH), 256>>>(inputs);
    pool2_kernel<<<(BBATCH*DD/4)/256, 256>>>();
    router_kernel<<<1, 1024>>>(router_w, router_b);
    merge_kernel<<<(DD*DD/4)/256, 256>>>(expert_w, expert_b);
    gemm_mma<<<dim3(DD/128, MM/128), 256, GEMM_SMEM>>>(out);
}

// round 16
// speedup vs baseline: 2.7208x; 1.7743x over previous
#include <cuda_runtime.h>
#include <cuda_fp16.h>
#include <math.h>
#include <stdint.h>

#define DD 1024
#define EE 8
#define BBATCH 4
#define SSEQ 4096
#define MM (BBATCH*SSEQ)

#define NPOOL 128
#define SCH (SSEQ/NPOOL)   // 32 rows per pool1 block

// GEMM tiling constants (needed for tiled global layout)
#define BKC 64
#define NKCH (DD/BKC)            // 16 k-chunks
#define PITCH 144                // bytes per 64-col fp16 row (128B data + 16B pad)
#define PITCH_H 72               // halves per row
#define TILE_B (128*PITCH)       // 18432 bytes per (tile,chunk)
#define TILE_H (TILE_B/2)        // 9216 halves
#define NMT (MM/128)             // 128 m-tiles
#define NNT (DD/128)             // 8 n-tiles

// -------- scratch (no allocations allowed) --------
__device__ float g_part[NPOOL*BBATCH*DD];
__device__ float g_pooled[BBATCH*DD];
__device__ float g_w[EE];
// tiled layouts: [tile][kchunk][128 rows][72 halves (64 data + 8 pad)]
__device__ __half g_ah[(size_t)NMT*NKCH*TILE_H];   // A * 1024, fp16, tiled
__device__ __half g_wh[(size_t)NNT*NKCH*TILE_H];   // merged W * 1024, fp16, tiled
__device__ float g_mb[DD];

// ============================================================
// pool1: mean-partials over S + fused A->fp16 (x1024), tiled write
// ============================================================
__global__ void pool1_kernel(const float* __restrict__ in) {
    const int chunk = blockIdx.x;
    const int b = blockIdx.y;
    const int d4 = threadIdx.x;  // 0..255 (float4 column group)
    const int r0 = b*SSEQ + chunk*SCH;
    const int kc  = d4 >> 4;          // k-chunk (64 cols each)
    const int cic = (d4 & 15) * 4;    // col within chunk
    const float4* p = reinterpret_cast<const float4*>(in) + (size_t)r0*(DD/4) + d4;
    float sx=0.f, sy=0.f, sz=0.f, sw=0.f;
    #pragma unroll 4
    for (int s = 0; s < SCH; s++) {
        float4 v = p[(size_t)s*(DD/4)];
        sx += v.x; sy += v.y; sz += v.z; sw += v.w;
        __half2 h01 = __floats2half2_rn(v.x*1024.f, v.y*1024.f);
        __half2 h23 = __floats2half2_rn(v.z*1024.f, v.w*1024.f);
        const int m = r0 + s;
        const size_t o = ((size_t)((m >> 7)*NKCH + kc)*128 + (m & 127))*PITCH_H + cic;
        *(uint2*)(g_ah + o) = make_uint2(*(uint32_t*)&h01, *(uint32_t*)&h23);
    }
    reinterpret_cast<float4*>(g_part)[(chunk*BBATCH + b)*(DD/4) + d4]
        = make_float4(sx, sy, sz, sw);
}

__global__ void pool2_kernel() {
    const int i = blockIdx.x*256 + threadIdx.x;   // 0..1023
    float sx=0.f, sy=0.f, sz=0.f, sw=0.f;
    for (int c = 0; c < NPOOL; c++) {
        float4 v = reinterpret_cast<const float4*>(g_part)[c*(BBATCH*DD/4) + i];
        sx += v.x; sy += v.y; sz += v.z; sw += v.w;
    }
    const float inv = 1.0f / (float)SSEQ;
    reinterpret_cast<float4*>(g_pooled)[i] = make_float4(sx*inv, sy*inv, sz*inv, sw*inv);
}

// ============================================================
// router
// ============================================================
__global__ void router_kernel(const float* __restrict__ rw, const float* __restrict__ rb) {
    __shared__ float sprob[BBATCH][EE];
    const int warp = threadIdx.x >> 5;
    const int lane = threadIdx.x & 31;
    const int b = warp >> 3;
    const int e = warp & 7;
    float sum = 0.f;
    for (int d = lane; d < DD; d += 32)
        sum = fmaf(g_pooled[b*DD + d], rw[e*DD + d], sum);
    #pragma unroll
    for (int o = 16; o; o >>= 1) sum += __shfl_xor_sync(0xffffffffu, sum, o);
    if (lane == 0) sprob[b][e] = sum + rb[e];
    __syncthreads();
    if (threadIdx.x < BBATCH) {
        const int bb = threadIdx.x;
        float mx = sprob[bb][0];
        #pragma unroll
        for (int ee = 1; ee < EE; ee++) mx = fmaxf(mx, sprob[bb][ee]);
        float ex[EE]; float den = 0.f;
        #pragma unroll
        for (int ee = 0; ee < EE; ee++) { ex[ee] = expf(sprob[bb][ee] - mx); den += ex[ee]; }
        #pragma unroll
        for (int ee = 0; ee < EE; ee++) sprob[bb][ee] = ex[ee] / den;
    }
    __syncthreads();
    if (threadIdx.x < EE) {
        float a = 0.f;
        #pragma unroll
        for (int bb = 0; bb < BBATCH; bb++) a += sprob[bb][threadIdx.x];
        g_w[threadIdx.x] = a * (1.0f / (float)BBATCH);
    }
}

// ============================================================
// merge: g_wh = fp16(1024 * sum_e w[e]*ew[e]) tiled, g_mb fp32
// ============================================================
__global__ void merge_kernel(const float* __restrict__ ew, const float* __restrict__ eb) {
    float w[EE];
    #pragma unroll
    for (int e = 0; e < EE; e++) w[e] = g_w[e];
    const size_t i = (size_t)blockIdx.x*256 + threadIdx.x;   // float4 index
    float sx=0.f, sy=0.f, sz=0.f, sw=0.f;
    #pragma unroll
    for (int e = 0; e < EE; e++) {
        float4 v = reinterpret_cast<const float4*>(ew)[(size_t)e*(DD*(size_t)DD/4) + i];
        sx = fmaf(w[e], v.x, sx); sy = fmaf(w[e], v.y, sy);
        sz = fmaf(w[e], v.z, sz); sw = fmaf(w[e], v.w, sw);
    }
    __half2 h01 = __floats2half2_rn(sx*1024.f, sy*1024.f);
    __half2 h23 = __floats2half2_rn(sz*1024.f, sw*1024.f);
    const size_t f = i*4;
    const int n = (int)(f / DD);
    const int k = (int)(f % DD);
    const size_t o = ((size_t)((n >> 7)*NKCH + (k >> 6))*128 + (n & 127))*PITCH_H + (k & 63);
    *(uint2*)(g_wh + o) = make_uint2(*(uint32_t*)&h01, *(uint32_t*)&h23);
    if (i < DD/4) {
        float bx=0.f, by=0.f, bz=0.f, bw=0.f;
        #pragma unroll
        for (int e = 0; e < EE; e++) {
            float4 v = reinterpret_cast<const float4*>(eb)[e*(DD/4) + i];
            bx = fmaf(w[e], v.x, bx); by = fmaf(w[e], v.y, by);
            bz = fmaf(w[e], v.z, bz); bw = fmaf(w[e], v.w, bw);
        }
        reinterpret_cast<float4*>(g_mb)[i] = make_float4(bx, by, bz, bw);
    }
}

// dummy: shifts ncu capture slot so index-5 launch is gemm_mma
__global__ void dummy_kernel() {}

// ============================================================
// GEMM: C = Ah x Wh^T * 2^-20 + b   (fp16 mma, fp32 acc)
// CTA 128x128, BK=64, 2-stage cp.async.bulk (2 instrs/chunk), 2 CTA/SM
// ============================================================

#define STAGE_B (2*TILE_B)       // 36864 (Ah tile + Wh tile)
#define GEMM_SMEM (2*STAGE_B)    // 73728

__device__ __forceinline__ uint32_t smem_u32(const void* p) {
    uint32_t a;
    asm("{ .reg .u64 t; cvta.to.shared.u64 t, %1; cvt.u32.u64 %0, t; }" : "=r"(a) : "l"(p));
    return a;
}
#define MBAR_INIT(addr, cnt) \
    asm volatile("mbarrier.init.shared.b64 [%0], %1;" :: "r"(addr), "r"(cnt) : "memory")
#define MBAR_EXPECT(addr, bytes) \
    asm volatile("mbarrier.arrive.expect_tx.shared.b64 _, [%0], %1;" :: "r"(addr), "r"(bytes) : "memory")
#define MBAR_WAIT(addr, par) do {                                                   \
    uint32_t _m = (addr); uint32_t _p = (par); uint32_t _done;                      \
    asm volatile("{\n\t.reg .pred p;\n\t"                                           \
        "mbarrier.try_wait.parity.acquire.cta.shared::cta.b64 p, [%1], %2;\n\t"     \
        "selp.b32 %0, 1, 0, p;\n\t}" : "=r"(_done) : "r"(_m), "r"(_p) : "memory");  \
    if (!_done) {                                                                   \
        asm volatile("{\n\t.reg .pred P1;\n\t"                                      \
            "WL_%=:\n\t"                                                            \
            "mbarrier.try_wait.parity.acquire.cta.shared::cta.b64 P1, [%0], %1, 0x989680;\n\t" \
            "@P1 bra.uni WD_%=;\n\t"                                                \
            "bra.uni WL_%=;\n\t"                                                    \
            "WD_%=:\n\t}" :: "r"(_m), "r"(_p) : "memory");                          \
    }                                                                               \
} while (0)

__device__ __forceinline__ void bulk_cp(uint32_t dst, const void* src, uint32_t bytes, uint32_t mbar) {
    asm volatile(
        "cp.async.bulk.shared::cta.global.mbarrier::complete_tx::bytes [%0], [%1], %2, [%3];"
        :: "r"(dst), "l"(src), "r"(bytes), "r"(mbar) : "memory");
}

__device__ __forceinline__ void mma16816(float acc[4], const uint32_t a[4], const uint32_t b[2]) {
    asm volatile(
        "mma.sync.aligned.m16n8k16.row.col.f32.f16.f16.f32 "
        "{%0,%1,%2,%3}, {%4,%5,%6,%7}, {%8,%9}, {%0,%1,%2,%3};"
        : "+f"(acc[0]), "+f"(acc[1]), "+f"(acc[2]), "+f"(acc[3])
        : "r"(a[0]), "r"(a[1]), "r"(a[2]), "r"(a[3]), "r"(b[0]), "r"(b[1]));
}

__device__ __forceinline__ void ldA(uint32_t fr[4][4], const char* As, int wm, int g, int t, int kk) {
    #pragma unroll
    for (int mt = 0; mt < 4; mt++) {
        const char* base = As + (wm*64 + mt*16)*PITCH + (kk + 2*t)*2;
        fr[mt][0] = *(const uint32_t*)(base + g*PITCH);
        fr[mt][1] = *(const uint32_t*)(base + (g+8)*PITCH);
        fr[mt][2] = *(const uint32_t*)(base + g*PITCH + 16);
        fr[mt][3] = *(const uint32_t*)(base + (g+8)*PITCH + 16);
    }
}
__device__ __forceinline__ void ldB(uint32_t fr[4][2], const char* Ws, int wn, int g, int t, int kk) {
    #pragma unroll
    for (int nt = 0; nt < 4; nt++) {
        const char* base = Ws + (wn*32 + nt*8 + g)*PITCH + (kk + 2*t)*2;
        fr[nt][0] = *(const uint32_t*)(base);
        fr[nt][1] = *(const uint32_t*)(base + 16);
    }
}

__global__ __launch_bounds__(256, 2) void gemm_mma(float* __restrict__ C) {
    extern __shared__ char sm[];
    __shared__ uint64_t mbar[2];
    const uint32_t sb = smem_u32(sm);
    const uint32_t mb0 = smem_u32(mbar);
    const int tid = threadIdx.x;
    const int w = tid >> 5;
    const int lane = tid & 31;
    const int wm = w >> 2;          // 0..1
    const int wn = w & 3;           // 0..3
    const int g = lane >> 2;        // 0..7
    const int t = lane & 3;         // 0..3
    const int m0 = blockIdx.y << 7;
    const int n0 = blockIdx.x << 7;

    // contiguous tiled sources for this CTA
    const __half* Asrc = g_ah + (size_t)blockIdx.y*NKCH*TILE_H;
    const __half* Wsrc = g_wh + (size_t)blockIdx.x*NKCH*TILE_H;

    if (tid == 0) { MBAR_INIT(mb0, 1u); MBAR_INIT(mb0 + 8, 1u); }
    __syncthreads();

#define ISSUE(kb) do {                                                        \
    const uint32_t mb = mb0 + ((kb) & 1)*8;                                   \
    MBAR_EXPECT(mb, (uint32_t)STAGE_B);                                       \
    bulk_cp(sb + ((kb) & 1)*STAGE_B,          Asrc + (size_t)(kb)*TILE_H,     \
            (uint32_t)TILE_B, mb);                                            \
    bulk_cp(sb + ((kb) & 1)*STAGE_B + TILE_B, Wsrc + (size_t)(kb)*TILE_H,     \
            (uint32_t)TILE_B, mb);                                            \
} while (0)

    float acc[4][4][4];
    #pragma unroll
    for (int mt = 0; mt < 4; mt++)
        #pragma unroll
        for (int nt = 0; nt < 4; nt++)
            #pragma unroll
            for (int c = 0; c < 4; c++) acc[mt][nt][c] = 0.f;

    if (tid == 0) { ISSUE(0); ISSUE(1); }

    for (int kb = 0; kb < NKCH; kb++) {
        MBAR_WAIT(mb0 + (kb & 1)*8, (kb >> 1) & 1);

        const char* base = sm + (kb & 1)*STAGE_B;
        uint32_t af[4][4], bf[4][2];
        #pragma unroll
        for (int kk = 0; kk < BKC; kk += 16) {
            ldB(bf, base + TILE_B, wn, g, t, kk);
            ldA(af, base, wm, g, t, kk);
            #pragma unroll
            for (int mt = 0; mt < 4; mt++)
                #pragma unroll
                for (int nt = 0; nt < 4; nt++)
                    mma16816(acc[mt][nt], af[mt], bf[nt]);
        }
        __syncthreads();
        if (tid == 0 && kb + 2 < NKCH) ISSUE(kb + 2);
    }

    // epilogue: undo 2^20 scale, add bias, store
    const float SC = 1.0f / (1024.0f * 1024.0f);
    #pragma unroll
    for (int nt = 0; nt < 4; nt++) {
        const int col = n0 + wn*32 + nt*8 + 2*t;
        const float b0 = g_mb[col];
        const float b1 = g_mb[col + 1];
        #pragma unroll
        for (int mt = 0; mt < 4; mt++) {
            const int row0 = m0 + wm*64 + mt*16 + g;
            float2 v0 = make_float2(fmaf(acc[mt][nt][0], SC, b0), fmaf(acc[mt][nt][1], SC, b1));
            float2 v1 = make_float2(fmaf(acc[mt][nt][2], SC, b0), fmaf(acc[mt][nt][3], SC, b1));
            *(float2*)(C + (size_t)row0*DD + col)       = v0;
            *(float2*)(C + (size_t)(row0 + 8)*DD + col) = v1;
        }
    }
#undef ISSUE
}

// ============================================================
// launch
// ============================================================
extern "C" void kernel_launch(void* const* d_in, const int* in_sizes, int n_in,
                              void* d_out, int out_size) {
    const float* inputs   = (const float*)d_in[0];
    const float* router_w = (const float*)d_in[1];
    const float* router_b = (const float*)d_in[2];
    const float* expert_w = (const float*)d_in[3];
    const float* expert_b = (const float*)d_in[4];
    float* out = (float*)d_out;

    cudaFuncSetAttribute(gemm_mma, cudaFuncAttributeMaxDynamicSharedMemorySize, GEMM_SMEM);

    pool1_kernel<<<dim3(NPOOL, BBATCH), 256>>>(inputs);       // launch 0
    pool2_kernel<<<(BBATCH*DD/4)/256, 256>>>();               // launch 1
    router_kernel<<<1, 1024>>>(router_w, router_b);           // launch 2
    merge_kernel<<<(DD*DD/4)/256, 256>>>(expert_w, expert_b); // launch 3
    dummy_kernel<<<1, 32>>>();                                // launch 4 (shifts ncu slot)
    gemm_mma<<<dim3(NNT, NMT), 256, GEMM_SMEM>>>(out);        // launch 5 <- profiled
}